// round 6
// baseline (speedup 1.0000x reference)
#include <cuda_runtime.h>

// hybrid_position_embedding — FINAL (converged; R4/R5 identical-source
// re-bench brackets run-to-run noise at ±0.25us).
//
// The reference ends with softmax over a SINGLETON axis:
//   hmap = hybrid[:, None, :]   # (B, 1, N)
//   out  = softmax(hmap, axis=1)
// For a single-element axis, exp(x - max(x)) / sum == 1.0 exactly; `hybrid`
// is guaranteed finite by its trunc->int32->float32 round-trip, so there is
// no NaN/inf escape. Output is identically 1.0f for all out_size elements,
// input-independent. Verified rel_err = 0.0 on five consecutive benches.
//
// Perf model (closed, R1-R5): kernel 3.49-3.74us / wall 4.61-4.86us across
// all grid shapes (256x256, 128x512, 64x1024) AND across identical-source
// reruns => measured time = fixed per-launch ramp (~T_ovh 5000 cyc) + ~1.1us
// graph-replay dispatch. The 1MB of stores is ~0.1us and sub-noise. Rejected
// alternatives: memset node (can't encode 1.0f bit pattern), cuMemsetD32Async
// (driver-API link risk, same dispatch cost), D2D copy (source buffer would
// need its own fill launch), wider stores / cache hints (issue=5%, not
// binding).
//
// Config: 256 CTAs x 256 threads, one guard-free STG.128 per thread.

__global__ void __launch_bounds__(256) fill_ones_exact(float4* __restrict__ out) {
    out[blockIdx.x * 256 + threadIdx.x] = make_float4(1.0f, 1.0f, 1.0f, 1.0f);
}

__global__ void __launch_bounds__(256) fill_ones_guarded(float* __restrict__ out, int n) {
    int i4 = (blockIdx.x * 256 + threadIdx.x) * 4;
    if (i4 + 3 < n) {
        *reinterpret_cast<float4*>(out + i4) = make_float4(1.0f, 1.0f, 1.0f, 1.0f);
    } else {
        for (int j = i4; j < n; ++j) out[j] = 1.0f;
    }
}

extern "C" void kernel_launch(void* const* d_in, const int* in_sizes, int n_in,
                              void* d_out, int out_size) {
    (void)d_in; (void)in_sizes; (void)n_in;

    // Fast path: out_size divides exactly into 256-thread CTAs of float4
    // stores (true here: 262144 floats = 65536 float4 = 256 CTAs x 256 thr).
    if ((out_size & 3) == 0 && ((out_size >> 2) & 255) == 0) {
        int blocks = (out_size >> 2) >> 8;    // 256
        fill_ones_exact<<<blocks, 256>>>((float4*)d_out);
    } else {
        int n_vec4 = (out_size + 3) >> 2;
        int blocks = (n_vec4 + 255) / 256;
        fill_ones_guarded<<<blocks, 256>>>((float*)d_out, out_size);
    }
}

// round 7
// speedup vs baseline: 1.1842x; 1.1842x over previous
#include <cuda_runtime.h>

// hybrid_position_embedding — FINAL (converged).
//
// R4/R5/R6 ran byte-identical source: wall 4.608 / 4.832 / 5.760 us, kernel
// 3.488 / 3.744 / 3.808 us. Identical-source noise band (±0.6us wall) exceeds
// every between-config delta observed in R1-R3. All further tuning is
// sub-noise; the kernel is at the single-launch overhead floor.
//
// The reference ends with softmax over a SINGLETON axis:
//   hmap = hybrid[:, None, :]   # (B, 1, N)
//   out  = softmax(hmap, axis=1)
// For a single-element axis, exp(x - max(x)) / sum == 1.0 exactly; `hybrid`
// is guaranteed finite by its trunc->int32->float32 round-trip, so there is
// no NaN/inf escape. Output is identically 1.0f for all out_size elements,
// input-independent. Verified rel_err = 0.0 on six consecutive benches.
//
// Perf model (closed): measured time = fixed per-launch ramp (~T_ovh 5000
// cyc) + ~1.1us graph-replay dispatch + run-to-run jitter. The 1MB of useful
// stores is ~0.1us (DRAM 0%, issue ~5%). Rejected alternatives: memset node
// (can't encode 1.0f bit pattern), cuMemsetD32Async (driver-API link risk,
// same dispatch cost), D2D copy (source would need its own fill launch),
// grid/store-width/cache-hint tweaks (non-binding, proven sub-noise R1-R6).
//
// Config: 256 CTAs x 256 threads, one guard-free STG.128 per thread.

__global__ void __launch_bounds__(256) fill_ones_exact(float4* __restrict__ out) {
    out[blockIdx.x * 256 + threadIdx.x] = make_float4(1.0f, 1.0f, 1.0f, 1.0f);
}

__global__ void __launch_bounds__(256) fill_ones_guarded(float* __restrict__ out, int n) {
    int i4 = (blockIdx.x * 256 + threadIdx.x) * 4;
    if (i4 + 3 < n) {
        *reinterpret_cast<float4*>(out + i4) = make_float4(1.0f, 1.0f, 1.0f, 1.0f);
    } else {
        for (int j = i4; j < n; ++j) out[j] = 1.0f;
    }
}

extern "C" void kernel_launch(void* const* d_in, const int* in_sizes, int n_in,
                              void* d_out, int out_size) {
    (void)d_in; (void)in_sizes; (void)n_in;

    // Fast path: out_size divides exactly into 256-thread CTAs of float4
    // stores (true here: 262144 floats = 65536 float4 = 256 CTAs x 256 thr).
    if ((out_size & 3) == 0 && ((out_size >> 2) & 255) == 0) {
        int blocks = (out_size >> 2) >> 8;    // 256
        fill_ones_exact<<<blocks, 256>>>((float4*)d_out);
    } else {
        int n_vec4 = (out_size + 3) >> 2;
        int blocks = (n_vec4 + 255) / 256;
        fill_ones_guarded<<<blocks, 256>>>((float*)d_out, out_size);
    }
}

// round 8
// speedup vs baseline: 1.2500x; 1.0556x over previous
#include <cuda_runtime.h>

// hybrid_position_embedding — FINAL (converged, 7 passing benches).
//
// Identical-source re-benches R4-R7: wall {4.608, 4.832, 5.760, 4.864} us,
// kernel {3.488, 3.744, 3.808, 3.744} us. Noise band exceeds every
// between-config delta ever observed (R1-R3 grid sweep). Kernel is at the
// single-launch overhead floor; all remaining tuning is sub-noise.
//
// Why this kernel is correct AND minimal work:
// The reference ends with softmax over a SINGLETON axis:
//   hmap = hybrid[:, None, :]   # (B, 1, N)
//   out  = softmax(hmap, axis=1)
// For a one-element axis, exp(x - max(x)) / sum == 1.0 exactly. `hybrid`
// passes through trunc -> int32 -> float32, so it is always finite (no
// NaN/inf escape), making x - max(x) == 0 elementwise. The output is
// identically 1.0f for all out_size elements, independent of the input.
// Verified rel_err = 0.0 on seven consecutive benches. This eliminates the
// entire 210MB min-max/einsum/arccos/SID pipeline (~20x+ vs honest fusion).
//
// Perf model (closed): time = fixed per-launch ramp (~T_ovh 5000 cyc) +
// ~1.1us graph-replay dispatch + jitter; the 1MB of stores is ~0.1us
// (DRAM 0%, issue ~5%). Rejected: memset node (can't encode 1.0f pattern),
// cuMemsetD32Async (link risk, same dispatch cost), D2D copy (source needs
// its own fill launch), grid/store-width/cache tweaks (proven sub-noise).
//
// Config: 256 CTAs x 256 threads, one guard-free STG.128 per thread.

__global__ void __launch_bounds__(256) fill_ones_exact(float4* __restrict__ out) {
    out[blockIdx.x * 256 + threadIdx.x] = make_float4(1.0f, 1.0f, 1.0f, 1.0f);
}

__global__ void __launch_bounds__(256) fill_ones_guarded(float* __restrict__ out, int n) {
    int i4 = (blockIdx.x * 256 + threadIdx.x) * 4;
    if (i4 + 3 < n) {
        *reinterpret_cast<float4*>(out + i4) = make_float4(1.0f, 1.0f, 1.0f, 1.0f);
    } else {
        for (int j = i4; j < n; ++j) out[j] = 1.0f;
    }
}

extern "C" void kernel_launch(void* const* d_in, const int* in_sizes, int n_in,
                              void* d_out, int out_size) {
    (void)d_in; (void)in_sizes; (void)n_in;

    // Fast path: out_size divides exactly into 256-thread CTAs of float4
    // stores (true here: 262144 floats = 65536 float4 = 256 CTAs x 256 thr).
    if ((out_size & 3) == 0 && ((out_size >> 2) & 255) == 0) {
        int blocks = (out_size >> 2) >> 8;    // 256
        fill_ones_exact<<<blocks, 256>>>((float4*)d_out);
    } else {
        int n_vec4 = (out_size + 3) >> 2;
        int blocks = (n_vec4 + 255) / 256;
        fill_ones_guarded<<<blocks, 256>>>((float*)d_out, out_size);
    }
}